// round 1
// baseline (speedup 1.0000x reference)
#include <cuda_runtime.h>
#include <stdint.h>

// Problem constants
// x: [B=16, C=128, H=224, W=224] fp32, perm: [B=16, 16] int32
// G=4, block = 56x56. Output block o <- input block inv_perm[o].
#define B_ 16
#define C_ 128
#define H_ 224
#define W_ 224
#define G_ 4
#define BH 56            // block height
#define W4 56            // W/4 float4 per row
#define BW4 14           // float4 per block col (56/4)
#define PER_BATCH_F4 (C_ * H_ * W4)   // 1,605,632 (divisible by 256)

__global__ __launch_bounds__(256) void block_shuffle_kernel(
    const float4* __restrict__ x,
    const int*    __restrict__ perm,
    float4*       __restrict__ out)
{
    __shared__ int s_inv[G_ * G_];

    const int idx = blockIdx.x * 256 + threadIdx.x;   // global float4 index
    const int b   = idx / PER_BATCH_F4;               // constant within CTA

    if (threadIdx.x < G_ * G_) {
        // perm[b][k] = o  (output position of input block k)
        // inv[o] = k  (input block feeding output position o)
        const int k = threadIdx.x;
        const int o = perm[b * (G_ * G_) + k];
        s_inv[o] = k;
    }
    __syncthreads();

    const int r   = idx - b * PER_BATCH_F4;  // index within batch
    const int w4  = r % W4;
    const int t   = r / W4;
    const int h   = t % H_;
    const int c   = t / H_;

    const int j = w4 / BW4;     // output block col
    const int i = h  / BH;      // output block row
    const int k = s_inv[i * G_ + j];
    const int si = k >> 2;
    const int sj = k & 3;

    const int sh  = si * BH  + (h  - i * BH);
    const int sw4 = sj * BW4 + (w4 - j * BW4);

    out[idx] = x[((b * C_ + c) * H_ + sh) * W4 + sw4];
}

extern "C" void kernel_launch(void* const* d_in, const int* in_sizes, int n_in,
                              void* d_out, int out_size)
{
    const float4* x    = (const float4*)d_in[0];
    const int*    perm = (const int*)d_in[1];
    float4*       out  = (float4*)d_out;

    const int total_f4 = B_ * PER_BATCH_F4;           // 25,690,112
    const int blocks   = total_f4 / 256;              // 100,352

    block_shuffle_kernel<<<blocks, 256>>>(x, perm, out);
}

// round 2
// speedup vs baseline: 1.1179x; 1.1179x over previous
#include <cuda_runtime.h>
#include <stdint.h>

// x: [B=16, C=128, H=224, W=224] fp32, perm: [B=16, 16] int32
// G=4, block = 56x56 per image plane. Output block o <- input block inv_perm[o].
//
// Geometry: grid = (H/16, C, B), blockDim = (56, 4).
//   threadIdx.x = w4 (float4 column, 0..55)
//   each (blockIdx.x, threadIdx.y) selects a 4-row group; all 4 rows lie in
//   the same 56-row output block (56 % 4 == 0), so the permutation lookup and
//   most index math happen once per thread, with 4 independent loads/stores
//   (MLP_p1 = 4).

#define G2 16

__global__ __launch_bounds__(224) void block_shuffle_kernel(
    const float4* __restrict__ x,
    const int*    __restrict__ perm,
    float4*       __restrict__ out)
{
    __shared__ int s_inv[G2];

    const int b = blockIdx.z;
    const int c = blockIdx.y;

    const int tid = threadIdx.y * 56 + threadIdx.x;
    if (tid < G2) {
        // perm[b][k] = o  (output slot of input block k)  ->  inv[o] = k
        const int o = perm[b * G2 + tid];
        s_inv[o] = tid;
    }
    __syncthreads();

    const int w4 = threadIdx.x;                              // 0..55
    const int h0 = (blockIdx.x * 4 + threadIdx.y) * 4;       // 0,4,...,220

    const int j = w4 / 14;          // output block col (small const div -> mul)
    const int i = h0 / 56;          // output block row (constant over 4 rows)
    const int k = s_inv[i * 4 + j];
    const int si = k >> 2;
    const int sj = k & 3;

    const int sh0 = si * 56 + (h0 - i * 56);
    const int sw4 = sj * 14 + (w4 - j * 14);

    const int plane = (b * 128 + c) * 224;                   // row base (in rows)
    const float4* __restrict__ src = x   + ((long)(plane + sh0)) * 56 + sw4;
    float4*       __restrict__ dst = out + ((long)(plane + h0 )) * 56 + w4;

    // 4 independent streaming loads, then 4 streaming stores (front-batched MLP)
    float4 v0 = __ldcs(src);
    float4 v1 = __ldcs(src +  56);
    float4 v2 = __ldcs(src + 112);
    float4 v3 = __ldcs(src + 168);

    __stcs(dst,       v0);
    __stcs(dst +  56, v1);
    __stcs(dst + 112, v2);
    __stcs(dst + 168, v3);
}

extern "C" void kernel_launch(void* const* d_in, const int* in_sizes, int n_in,
                              void* d_out, int out_size)
{
    const float4* x    = (const float4*)d_in[0];
    const int*    perm = (const int*)d_in[1];
    float4*       out  = (float4*)d_out;

    dim3 grid(224 / 16, 128, 16);   // (14, C, B)
    dim3 block(56, 4);
    block_shuffle_kernel<<<grid, block>>>(x, perm, out);
}

// round 3
// speedup vs baseline: 1.1215x; 1.0032x over previous
#include <cuda_runtime.h>
#include <stdint.h>

// x: [B=16, C=128, H=224, W=224] fp32, perm: [B=16, 16] int32
// G=4, block = 56x56 per image plane. Output block o <- input block inv_perm[o].
//
// Geometry: grid = (H/32, C, B) = (7, 128, 16), blockDim = (56, 4).
//   threadIdx.x = w4 (float4 column, 0..55)
//   each (blockIdx.x, threadIdx.y) selects an 8-row group; all 8 rows lie in
//   the same 56-row output block (56 % 8 == 0), so the permutation lookup and
//   index math happen once per thread, with 8 independent front-batched
//   loads followed by 8 stores (MLP_p1 = 8).

#define G2 16

__global__ __launch_bounds__(224) void block_shuffle_kernel(
    const float4* __restrict__ x,
    const int*    __restrict__ perm,
    float4*       __restrict__ out)
{
    __shared__ int s_inv[G2];

    const int b = blockIdx.z;
    const int c = blockIdx.y;

    const int tid = threadIdx.y * 56 + threadIdx.x;
    if (tid < G2) {
        // perm[b][k] = o  (output slot of input block k)  ->  inv[o] = k
        const int o = perm[b * G2 + tid];
        s_inv[o] = tid;
    }
    __syncthreads();

    const int w4 = threadIdx.x;                              // 0..55
    const int h0 = (blockIdx.x * 4 + threadIdx.y) * 8;       // 0,8,...,216

    const int j = w4 / 14;          // output block col (const-div -> mul)
    const int i = h0 / 56;          // output block row (constant over 8 rows)
    const int k = s_inv[i * 4 + j];
    const int si = k >> 2;
    const int sj = k & 3;

    const int sh0 = si * 56 + (h0 - i * 56);
    const int sw4 = sj * 14 + (w4 - j * 14);

    const int plane = (b * 128 + c) * 224;                   // row base (in rows)
    const float4* __restrict__ src = x   + ((long)(plane + sh0)) * 56 + sw4;
    float4*       __restrict__ dst = out + ((long)(plane + h0 )) * 56 + w4;

    // 8 independent streaming loads (front-batched), then 8 streaming stores
    float4 v0 = __ldcs(src);
    float4 v1 = __ldcs(src +  56);
    float4 v2 = __ldcs(src + 112);
    float4 v3 = __ldcs(src + 168);
    float4 v4 = __ldcs(src + 224);
    float4 v5 = __ldcs(src + 280);
    float4 v6 = __ldcs(src + 336);
    float4 v7 = __ldcs(src + 392);

    __stcs(dst,       v0);
    __stcs(dst +  56, v1);
    __stcs(dst + 112, v2);
    __stcs(dst + 168, v3);
    __stcs(dst + 224, v4);
    __stcs(dst + 280, v5);
    __stcs(dst + 336, v6);
    __stcs(dst + 392, v7);
}

extern "C" void kernel_launch(void* const* d_in, const int* in_sizes, int n_in,
                              void* d_out, int out_size)
{
    const float4* x    = (const float4*)d_in[0];
    const int*    perm = (const int*)d_in[1];
    float4*       out  = (float4*)d_out;

    dim3 grid(224 / 32, 128, 16);   // (7, C, B)
    dim3 block(56, 4);
    block_shuffle_kernel<<<grid, block>>>(x, perm, out);
}